// round 7
// baseline (speedup 1.0000x reference)
#include <cuda_runtime.h>
#include <cstdint>

#define DDIM 256
#define NROWS 65536
#define KCODES 1024
#define BM 128
#define BN 128
#define BKB 64            // bytes per k-stage
#define NKS 12            // 4 (ah*bh) + 8 (ah*bl | al*bh)
#define ASTRIDE 80        // smem row stride in bytes (conflict-free)
#define INFV 3.4e38f
#define SWQ (1.0f/16256.0f)
#define OUTRPB 16
#define OUTBLK (NROWS/OUTRPB)
#define RGRID 256

__device__ int8_t g_zah[(size_t)NROWS * DDIM];   // 16 MB
__device__ int8_t g_zal[(size_t)NROWS * DDIM];   // 16 MB
__device__ int8_t g_wbh[(size_t)KCODES * DDIM];
__device__ int8_t g_wbl[(size_t)KCODES * DDIM];
__device__ float g_sz[NROWS];
__device__ float g_me[NROWS];
__device__ float g_wt[DDIM * KCODES];            // transposed fp32 codebook (refine)
__device__ float g_cnorm[KCODES];
__device__ int   g_idx[NROWS];
__device__ int   g_flaglist[NROWS];
__device__ int   g_flagcount;
__device__ float g_partial[OUTBLK];

// ---------------- helpers ----------------
__device__ __forceinline__ void cp16(unsigned saddr, const void* gaddr) {
    asm volatile("cp.async.cg.shared.global [%0], [%1], 16;\n" :: "r"(saddr), "l"(gaddr) : "memory");
}
__device__ __forceinline__ void cp_commit() { asm volatile("cp.async.commit_group;\n" ::: "memory"); }
template<int P> __device__ __forceinline__ void cp_wait() {
    asm volatile("cp.async.wait_group %0;\n" :: "n"(P) : "memory");
}
__device__ __forceinline__ void ldsm4(unsigned a, unsigned &r0, unsigned &r1, unsigned &r2, unsigned &r3) {
    asm volatile("ldmatrix.sync.aligned.m8n8.x4.shared.b16 {%0,%1,%2,%3}, [%4];"
                 : "=r"(r0), "=r"(r1), "=r"(r2), "=r"(r3) : "r"(a));
}
__device__ __forceinline__ void mma_s8(int* c, const unsigned* a, const unsigned* b) {
    asm volatile("mma.sync.aligned.m16n8k32.row.col.s32.s8.s8.s32 "
                 "{%0,%1,%2,%3}, {%4,%5,%6,%7}, {%8,%9}, {%0,%1,%2,%3};"
                 : "+r"(c[0]), "+r"(c[1]), "+r"(c[2]), "+r"(c[3])
                 : "r"(a[0]), "r"(a[1]), "r"(a[2]), "r"(a[3]), "r"(b[0]), "r"(b[1]));
}
__device__ __forceinline__ bool lexless(float v, int i, float w, int j) {
    return v < w || (v == w && i < j);
}
__device__ __forceinline__ void top2_merge(float &v1, int &i1, float &v2, int &i2,
                                           float w1, int j1, float w2, int j2) {
    if (lexless(w1, j1, v1, i1)) {
        float nv2; int ni2;
        if (lexless(v1, i1, w2, j2)) { nv2 = v1; ni2 = i1; } else { nv2 = w2; ni2 = j2; }
        v1 = w1; i1 = j1; v2 = nv2; i2 = ni2;
    } else if (lexless(w1, j1, v2, i2)) {
        v2 = w1; i2 = j1;
    }
}
__device__ __forceinline__ unsigned pack4(int b0, int b1, int b2, int b3) {
    return (b0 & 0xff) | ((b1 & 0xff) << 8) | ((b2 & 0xff) << 16) | ((b3 & 0xff) << 24);
}

// ---------------- prep: per-row 15-bit quantization, 2 int8 limbs ----------------
__global__ void quant_z_kernel(const float* __restrict__ z) {
    int warp = threadIdx.x >> 5, lane = threadIdx.x & 31;
    int row = blockIdx.x * 8 + warp;
    const float4* zr = (const float4*)(z + (size_t)row * DDIM);
    float4 v0 = zr[lane * 2], v1 = zr[lane * 2 + 1];
    float v[8] = {v0.x, v0.y, v0.z, v0.w, v1.x, v1.y, v1.z, v1.w};
    float mx = 0.f, sm = 0.f;
    #pragma unroll
    for (int i = 0; i < 8; i++) { float a = fabsf(v[i]); mx = fmaxf(mx, a); sm += a; }
    #pragma unroll
    for (int o = 16; o; o >>= 1) {
        mx = fmaxf(mx, __shfl_xor_sync(0xffffffffu, mx, o));
        sm += __shfl_xor_sync(0xffffffffu, sm, o);
    }
    float inv = (mx > 0.f) ? 16256.f / mx : 0.f;
    float sz  = (mx > 0.f) ? mx / 16256.f : 0.f;
    int ah[8], al[8];
    #pragma unroll
    for (int i = 0; i < 8; i++) {
        int q = (int)rintf(v[i] * inv);
        q = max(-16256, min(16256, q));
        ah[i] = (q + 64) >> 7;            // [-127,127]
        al[i] = q - (ah[i] << 7);         // [-64,63]
    }
    size_t off = (size_t)row * DDIM + lane * 8;
    *(uint2*)(g_zah + off) = make_uint2(pack4(ah[0],ah[1],ah[2],ah[3]), pack4(ah[4],ah[5],ah[6],ah[7]));
    *(uint2*)(g_zal + off) = make_uint2(pack4(al[0],al[1],al[2],al[3]), pack4(al[4],al[5],al[6],al[7]));
    if (lane == 0) {
        g_sz[row] = sz;
        // E >= 0.5*sw*Sum|z| + (Sw/2<=128)*sz + ll(<=256*64*64*sz*sw=64.55sz) + cross + fp slack
        g_me[row] = 0.5f * SWQ * sm + 192.7f * sz + 1e-3f;
    }
}

__global__ void quant_w_kernel(const float* __restrict__ w) {
    if (blockIdx.x == 0 && threadIdx.x == 0) g_flagcount = 0;
    int warp = threadIdx.x >> 5, lane = threadIdx.x & 31;
    int row = blockIdx.x * 8 + warp;
    const float4* wr = (const float4*)(w + (size_t)row * DDIM);
    float4 v0 = wr[lane * 2], v1 = wr[lane * 2 + 1];
    float v[8] = {v0.x, v0.y, v0.z, v0.w, v1.x, v1.y, v1.z, v1.w};
    int bh[8], bl[8];
    #pragma unroll
    for (int i = 0; i < 8; i++) {
        int q = (int)rintf(v[i] * 16256.f);
        q = max(-16256, min(16256, q));
        bh[i] = (q + 64) >> 7;
        bl[i] = q - (bh[i] << 7);
    }
    size_t off = (size_t)row * DDIM + lane * 8;
    *(uint2*)(g_wbh + off) = make_uint2(pack4(bh[0],bh[1],bh[2],bh[3]), pack4(bh[4],bh[5],bh[6],bh[7]));
    *(uint2*)(g_wbl + off) = make_uint2(pack4(bl[0],bl[1],bl[2],bl[3]), pack4(bl[4],bl[5],bl[6],bl[7]));
}

__global__ void transpose_w_kernel(const float* __restrict__ w) {
    __shared__ float t[32][33];
    int kb = blockIdx.x * 32, db = blockIdx.y * 32;
    int tx = threadIdx.x, ty = threadIdx.y;   // 32 x 8
    #pragma unroll
    for (int i = 0; i < 4; i++)
        t[ty + i * 8][tx] = w[(size_t)(kb + ty + i * 8) * DDIM + db + tx];
    __syncthreads();
    #pragma unroll
    for (int i = 0; i < 4; i++)
        g_wt[(size_t)(db + ty + i * 8) * KCODES + kb + tx] = t[tx][ty + i * 8];
}

__global__ void cnorm_kernel(const float* __restrict__ w, int K) {
    int k = blockIdx.x * 8 + (threadIdx.x >> 5);
    int lane = threadIdx.x & 31;
    if (k >= K) return;
    const float4* wr = (const float4*)(w + (size_t)k * DDIM);
    float4 v0 = wr[lane];
    float4 v1 = wr[lane + 32];
    float s = v0.x*v0.x + v0.y*v0.y + v0.z*v0.z + v0.w*v0.w
            + v1.x*v1.x + v1.y*v1.y + v1.z*v1.z + v1.w*v1.w;
    #pragma unroll
    for (int m = 16; m; m >>= 1) s += __shfl_xor_sync(0xffffffffu, s, m);
    if (lane == 0) g_cnorm[k] = s;
}

// ---------------- int8 GEMM stage loader (limb remap) ----------------
__device__ __forceinline__ void load_stage(unsigned as_, unsigned bs_,
                                           int rowBase, int kc, int ks, int tid) {
    const int8_t* Aarr; int ca;
    const int8_t* Barr; int cb;
    if (ks < 4) { Aarr = g_zah; ca = ks * 64; Barr = g_wbh; cb = ks * 64; }
    else {
        int v = (ks - 4) * 64;
        Aarr = (v < 256) ? g_zah : g_zal; ca = (v < 256) ? v : v - 256;
        Barr = (v < 256) ? g_wbl : g_wbh; cb = (v < 256) ? v : v - 256;
    }
    {   // A: 128 rows x 64B = 512 chunks, one per thread
        int r = tid >> 2, s = tid & 3;
        cp16(as_ + (unsigned)(r * ASTRIDE + s * 16),
             Aarr + (size_t)(rowBase + r) * DDIM + ca + s * 16);
        // B: 128 codes x 64B = 512 chunks, one per thread
        cp16(bs_ + (unsigned)(r * ASTRIDE + s * 16),
             Barr + (size_t)(kc + r) * DDIM + cb + s * 16);
    }
    cp_commit();
}

__device__ __forceinline__ void compute_ks(int acc[2][4][4], unsigned abase, unsigned bbase,
                                           int wm0, int wn0, int lane) {
    #pragma unroll
    for (int kk = 0; kk < BKB; kk += 32) {
        unsigned a[2][4];
        #pragma unroll
        for (int i = 0; i < 2; i++) {
            int arow = wm0 + i * 16 + (lane & 15);
            int acol = kk + ((lane >> 4) << 4);
            ldsm4(abase + (unsigned)(arow * ASTRIDE + acol),
                  a[i][0], a[i][1], a[i][2], a[i][3]);
        }
        unsigned b[4][2];
        #pragma unroll
        for (int p = 0; p < 2; p++) {
            int brow = wn0 + p * 16 + (lane & 7) + ((lane >> 4) << 3);
            int bcol = kk + (((lane >> 3) & 1) << 4);
            ldsm4(bbase + (unsigned)(brow * ASTRIDE + bcol),
                  b[2*p][0], b[2*p][1], b[2*p+1][0], b[2*p+1][1]);
        }
        #pragma unroll
        for (int i = 0; i < 2; i++)
            #pragma unroll
            for (int j = 0; j < 4; j++)
                mma_s8(acc[i][j], a[i], b[j]);
    }
}

// ---------------- main int8 GEMM + certified top2 ----------------
__global__ void __launch_bounds__(512, 1)
gemm_kernel(int N, int K)
{
    extern __shared__ __align__(16) int8_t dyn[];
    // layout: A stage0, A stage1, B stage0, B stage1
    const unsigned ABYT = BM * ASTRIDE;          // 10240
    const unsigned BBYT = BN * ASTRIDE;          // 10240
    __shared__ float4 s_part[4][BM];
    __shared__ float4 s_run[BM];
    __shared__ float  s_cn[BN];
    __shared__ float  s_sz[BM];
    __shared__ float  s_me[BM];

    const int tid  = threadIdx.x;
    const int lane = tid & 31;
    const int warp = tid >> 5;      // 0..15
    const int mw   = warp & 3;      // 4 m-warps
    const int nw   = warp >> 2;     // 4 n-warps
    const int wm0  = mw * 32;
    const int wn0  = nw * 32;
    const int rowBase = blockIdx.x * BM;

    unsigned sbase = (unsigned)__cvta_generic_to_shared(dyn);
    unsigned aS[2] = {sbase, sbase + ABYT};
    unsigned bS[2] = {sbase + 2 * ABYT, sbase + 2 * ABYT + BBYT};

    if (tid < BM) {
        s_run[tid] = make_float4(INFV, __int_as_float(0x7fffffff),
                                 INFV, __int_as_float(0x7fffffff));
        s_sz[tid] = g_sz[rowBase + tid];
        s_me[tid] = g_me[rowBase + tid];
    }

    load_stage(aS[0], bS[0], rowBase, 0, 0, tid);

    for (int kc = 0; kc < K; kc += BN) {
        if (tid < BN) s_cn[tid] = g_cnorm[kc + tid];

        int acc1[2][4][4], acc2[2][4][4];
        #pragma unroll
        for (int i = 0; i < 2; i++)
            #pragma unroll
            for (int j = 0; j < 4; j++)
                #pragma unroll
                for (int c = 0; c < 4; c++) { acc1[i][j][c] = 0; acc2[i][j][c] = 0; }

        for (int ks = 0; ks < NKS; ks++) {
            int buf = ks & 1;
            cp_wait<0>();
            __syncthreads();
            if (ks + 1 < NKS)
                load_stage(aS[buf ^ 1], bS[buf ^ 1], rowBase, kc, ks + 1, tid);
            else if (kc + BN < K)
                load_stage(aS[buf ^ 1], bS[buf ^ 1], rowBase, kc + BN, 0, tid);

            if (ks < 4) compute_ks(acc1, aS[buf], bS[buf], wm0, wn0, lane);
            else        compute_ks(acc2, aS[buf], bS[buf], wm0, wn0, lane);
        }
        __syncthreads();

        // epilogue: score = cn[k] - 2*sz*SWQ*(16384*acc1 + 128*acc2); per-row top2
        #pragma unroll
        for (int i = 0; i < 2; i++) {
            #pragma unroll
            for (int h = 0; h < 2; h++) {
                int rloc = wm0 + i * 16 + (lane >> 2) + h * 8;
                float m2 = -2.f * s_sz[rloc] * SWQ;
                float v1 = INFV; int i1 = 0x7fffffff;
                float v2 = INFV; int i2 = 0x7fffffff;
                #pragma unroll
                for (int j = 0; j < 4; j++) {
                    #pragma unroll
                    for (int c = 0; c < 2; c++) {
                        int col = wn0 + j * 8 + 2 * (lane & 3) + c;
                        float f = fmaf(16384.f, (float)acc1[i][j][h*2+c],
                                       128.f * (float)acc2[i][j][h*2+c]);
                        float val = fmaf(m2, f, s_cn[col]);
                        int idx = kc + col;
                        if (lexless(val, idx, v1, i1)) { v2 = v1; i2 = i1; v1 = val; i1 = idx; }
                        else if (lexless(val, idx, v2, i2)) { v2 = val; i2 = idx; }
                    }
                }
                #pragma unroll
                for (int off = 1; off < 4; off <<= 1) {
                    float ov1 = __shfl_xor_sync(0xffffffffu, v1, off);
                    int   oi1 = __shfl_xor_sync(0xffffffffu, i1, off);
                    float ov2 = __shfl_xor_sync(0xffffffffu, v2, off);
                    int   oi2 = __shfl_xor_sync(0xffffffffu, i2, off);
                    top2_merge(v1, i1, v2, i2, ov1, oi1, ov2, oi2);
                }
                if ((lane & 3) == 0)
                    s_part[nw][rloc] = make_float4(v1, __int_as_float(i1), v2, __int_as_float(i2));
            }
        }
        __syncthreads();
        if (tid < BM) {
            float4 r = s_run[tid];
            float r1 = r.x; int ri1 = __float_as_int(r.y);
            float r2 = r.z; int ri2 = __float_as_int(r.w);
            #pragma unroll
            for (int g = 0; g < 4; g++) {
                float4 p = s_part[g][tid];
                top2_merge(r1, ri1, r2, ri2, p.x, __float_as_int(p.y), p.z, __float_as_int(p.w));
            }
            s_run[tid] = make_float4(r1, __int_as_float(ri1), r2, __int_as_float(ri2));
        }
        __syncthreads();
    }

    if (tid < BM) {
        float4 r = s_run[tid];
        int row = rowBase + tid;
        g_idx[row] = __float_as_int(r.y);
        if (r.z - r.x <= 2.f * s_me[tid]) {
            int pos = atomicAdd(&g_flagcount, 1);
            g_flaglist[pos] = row;
        }
    }
}

// ---------------- exact refine of flagged rows (wT-based, FMA-bound) ----------------
__global__ void refine_kernel(const float* __restrict__ z, int K) {
    __shared__ __align__(16) float zs[8][260];
    __shared__ int   rowids[8];
    __shared__ float sbv[8][8];
    __shared__ int   sbi[8][8];

    const int tid  = threadIdx.x;
    const int lane = tid & 31;
    const int warp = tid >> 5;
    const int fcount = g_flagcount;

    for (int base = blockIdx.x * 8; base < fcount; base += gridDim.x * 8) {
        int cnt = min(8, fcount - base);
        if (tid < cnt) rowids[tid] = g_flaglist[base + tid];
        __syncthreads();
        for (int e = tid; e < cnt * 256; e += 256)
            zs[e >> 8][e & 255] = z[(size_t)rowids[e >> 8] * DDIM + (e & 255)];
        __syncthreads();

        float bv[8]; int bi[8];
        #pragma unroll
        for (int r = 0; r < 8; r++) { bv[r] = INFV; bi[r] = 0x7fffffff; }

        #pragma unroll 1
        for (int p = 0; p < 4; p++) {
            int k = p * 256 + tid;
            float acc[8];
            #pragma unroll
            for (int r = 0; r < 8; r++) acc[r] = 0.f;
            #pragma unroll 4
            for (int d4 = 0; d4 < 64; d4++) {
                float w0 = g_wt[(size_t)(d4 * 4 + 0) * KCODES + k];
                float w1 = g_wt[(size_t)(d4 * 4 + 1) * KCODES + k];
                float w2 = g_wt[(size_t)(d4 * 4 + 2) * KCODES + k];
                float w3 = g_wt[(size_t)(d4 * 4 + 3) * KCODES + k];
                #pragma unroll
                for (int r = 0; r < 8; r++) {
                    float4 zv = *(const float4*)&zs[r][d4 * 4];
                    acc[r] = fmaf(zv.x, w0, acc[r]);
                    acc[r] = fmaf(zv.y, w1, acc[r]);
                    acc[r] = fmaf(zv.z, w2, acc[r]);
                    acc[r] = fmaf(zv.w, w3, acc[r]);
                }
            }
            float cn = g_cnorm[k];
            #pragma unroll
            for (int r = 0; r < 8; r++) {
                float val = fmaf(-2.f, acc[r], cn);
                if (lexless(val, k, bv[r], bi[r])) { bv[r] = val; bi[r] = k; }
            }
        }

        #pragma unroll
        for (int r = 0; r < 8; r++) {
            float v = bv[r]; int i = bi[r];
            #pragma unroll
            for (int off = 16; off; off >>= 1) {
                float ov = __shfl_xor_sync(0xffffffffu, v, off);
                int   oi = __shfl_xor_sync(0xffffffffu, i, off);
                if (lexless(ov, oi, v, i)) { v = ov; i = oi; }
            }
            if (lane == 0) { sbv[warp][r] = v; sbi[warp][r] = i; }
        }
        __syncthreads();
        if (tid < cnt) {
            float v = sbv[0][tid]; int i = sbi[0][tid];
            #pragma unroll
            for (int wq = 1; wq < 8; wq++)
                if (lexless(sbv[wq][tid], sbi[wq][tid], v, i)) { v = sbv[wq][tid]; i = sbi[wq][tid]; }
            g_idx[rowids[tid]] = i;
        }
        __syncthreads();
    }
}

// ---------------- coalesced output assembly ----------------
__global__ void output_kernel(const float* __restrict__ z, const float* __restrict__ w,
                              float* __restrict__ out, int N)
{
    __shared__ int s_idx[OUTRPB];
    __shared__ float s_red[256];
    const int tid = threadIdx.x;
    const int base = blockIdx.x * OUTRPB;

    float* out_zq  = out + 1;
    float* out_idx = out + 1 + (size_t)N * DDIM;

    if (tid < OUTRPB) {
        int ix = g_idx[base + tid];
        s_idx[tid] = ix;
        out_idx[base + tid] = (float)ix;
    }
    __syncthreads();

    float lsum = 0.f;
    #pragma unroll 4
    for (int i = tid; i < OUTRPB * DDIM; i += 256) {
        int r = i >> 8, d = i & 255;
        float wv = w[(size_t)s_idx[r] * DDIM + d];
        float zv = z[(size_t)(base + r) * DDIM + d];
        float df = wv - zv;
        lsum += df * df;
        out_zq[(size_t)(base + r) * DDIM + d] = wv;
    }

    s_red[tid] = lsum;
    __syncthreads();
    #pragma unroll
    for (int m = 128; m; m >>= 1) {
        if (tid < m) s_red[tid] += s_red[tid + m];
        __syncthreads();
    }
    if (tid == 0) g_partial[blockIdx.x] = s_red[0];
}

__global__ void finalize_kernel(float* __restrict__ out, int nblocks, float scale) {
    __shared__ float s[512];
    int t = threadIdx.x;
    float v = 0.f;
    for (int i = t; i < nblocks; i += 512) v += g_partial[i];
    s[t] = v;
    __syncthreads();
    #pragma unroll
    for (int m = 256; m; m >>= 1) {
        if (t < m) s[t] += s[t + m];
        __syncthreads();
    }
    if (t == 0) out[0] = s[0] * scale;
}

extern "C" void kernel_launch(void* const* d_in, const int* in_sizes, int n_in,
                              void* d_out, int out_size) {
    const float* z = (const float*)d_in[0];
    const float* w = (const float*)d_in[1];
    float* out = (float*)d_out;

    int N = in_sizes[0] / DDIM;   // 65536
    int K = in_sizes[1] / DDIM;   // 1024

    const int dynsmem = 2 * (BM * ASTRIDE) + 2 * (BN * ASTRIDE);   // 40960 B
    cudaFuncSetAttribute(gemm_kernel, cudaFuncAttributeMaxDynamicSharedMemorySize, dynsmem);

    quant_z_kernel<<<N / 8, 256>>>(z);
    quant_w_kernel<<<K / 8, 256>>>(w);
    transpose_w_kernel<<<dim3(K / 32, DDIM / 32), dim3(32, 8)>>>(w);
    cnorm_kernel<<<(K + 7) / 8, 256>>>(w, K);
    gemm_kernel<<<N / BM, 512, dynsmem>>>(N, K);
    refine_kernel<<<RGRID, 256>>>(z, K);
    output_kernel<<<N / OUTRPB, 256>>>(z, w, out, N);
    float scale = 0.25f / ((float)N * (float)DDIM);
    finalize_kernel<<<1, 512>>>(out, N / OUTRPB, scale);
}

// round 8
// speedup vs baseline: 2.6628x; 2.6628x over previous
#include <cuda_runtime.h>
#include <cuda_fp16.h>
#include <cstdint>

#define DDIM 256
#define NROWS 65536
#define KCODES 1024
#define BM 128
#define BN 128
#define BK 64
#define KS 4                 // 256/64 k-stages per code chunk
#define ASTRIDE 72           // padded fp16 stride (conflict-free LDSM, proven R6)
#define INFV 3.4e38f
#define OUTRPB 16
#define OUTBLK (NROWS/OUTRPB)
#define RGRID 256

__device__ __half g_zh[(size_t)NROWS * DDIM];    // 32 MB
__device__ __half g_wh[(size_t)KCODES * DDIM];
__device__ float g_wt[DDIM * KCODES];            // transposed fp32 codebook (refine)
__device__ float g_cnorm[KCODES];
__device__ float g_me[NROWS];                    // per-row certified margin
__device__ int   g_wmaxbits;                     // max ||w_k|| (float bits)
__device__ int   g_dwmaxbits;                    // max ||dw_k||
__device__ int   g_idx[NROWS];
__device__ int   g_flaglist[NROWS];
__device__ int   g_flagcount;
__device__ float g_partial[OUTBLK];

// ---------------- init ----------------
__global__ void init_kernel() {
    g_flagcount = 0;
    g_wmaxbits = 0;
    g_dwmaxbits = 0;
}

// ---------------- prep ----------------
__global__ void quant_w_kernel(const float* __restrict__ w) {
    int warp = threadIdx.x >> 5, lane = threadIdx.x & 31;
    int row = blockIdx.x * 8 + warp;
    const float4* wr = (const float4*)(w + (size_t)row * DDIM);
    float4 v0 = wr[lane * 2], v1 = wr[lane * 2 + 1];
    float v[8] = {v0.x, v0.y, v0.z, v0.w, v1.x, v1.y, v1.z, v1.w};
    __half h[8];
    float sd2 = 0.f, sw2 = 0.f;
    #pragma unroll
    for (int i = 0; i < 8; i++) {
        h[i] = __float2half_rn(v[i]);
        float d = v[i] - __half2float(h[i]);   // exact
        sd2 += d * d;
        sw2 += v[i] * v[i];
    }
    #pragma unroll
    for (int o = 16; o; o >>= 1) {
        sd2 += __shfl_xor_sync(0xffffffffu, sd2, o);
        sw2 += __shfl_xor_sync(0xffffffffu, sw2, o);
    }
    *(uint4*)(g_wh + (size_t)row * DDIM + lane * 8) = *(uint4*)h;
    if (lane == 0) {
        float wn  = sqrtf(sw2) * 1.0001f + 1e-8f;
        float dwn = sqrtf(sd2) * 1.0001f + 1e-8f;
        atomicMax(&g_wmaxbits, __float_as_int(wn));
        atomicMax(&g_dwmaxbits, __float_as_int(dwn));
    }
}

__global__ void quant_z_kernel(const float* __restrict__ z) {
    int warp = threadIdx.x >> 5, lane = threadIdx.x & 31;
    int row = blockIdx.x * 8 + warp;
    const float4* zr = (const float4*)(z + (size_t)row * DDIM);
    float4 v0 = zr[lane * 2], v1 = zr[lane * 2 + 1];
    float v[8] = {v0.x, v0.y, v0.z, v0.w, v1.x, v1.y, v1.z, v1.w};
    __half h[8];
    float sd2 = 0.f, sh2 = 0.f;
    #pragma unroll
    for (int i = 0; i < 8; i++) {
        h[i] = __float2half_rn(v[i]);
        float zh = __half2float(h[i]);
        float d = v[i] - zh;                    // exact
        sd2 += d * d;
        sh2 += zh * zh;
    }
    #pragma unroll
    for (int o = 16; o; o >>= 1) {
        sd2 += __shfl_xor_sync(0xffffffffu, sd2, o);
        sh2 += __shfl_xor_sync(0xffffffffu, sh2, o);
    }
    *(uint4*)(g_zh + (size_t)row * DDIM + lane * 8) = *(uint4*)h;
    if (lane == 0) {
        float dzn = sqrtf(sd2) * 1.0001f + 1e-8f;
        float zhn = sqrtf(sh2) * 1.0001f;
        float wmax  = __int_as_float(g_wmaxbits);
        float dwmax = __int_as_float(g_dwmaxbits);
        g_me[row] = 4.f * (dzn * wmax + zhn * dwmax) + 0.01f;
    }
}

__global__ void transpose_w_kernel(const float* __restrict__ w) {
    __shared__ float t[32][33];
    int kb = blockIdx.x * 32, db = blockIdx.y * 32;
    int tx = threadIdx.x, ty = threadIdx.y;   // 32 x 8
    #pragma unroll
    for (int i = 0; i < 4; i++)
        t[ty + i * 8][tx] = w[(size_t)(kb + ty + i * 8) * DDIM + db + tx];
    __syncthreads();
    #pragma unroll
    for (int i = 0; i < 4; i++)
        g_wt[(size_t)(db + ty + i * 8) * KCODES + kb + tx] = t[tx][ty + i * 8];
}

__global__ void cnorm_kernel(const float* __restrict__ w, int K) {
    int k = blockIdx.x * 8 + (threadIdx.x >> 5);
    int lane = threadIdx.x & 31;
    if (k >= K) return;
    const float4* wr = (const float4*)(w + (size_t)k * DDIM);
    float4 v0 = wr[lane];
    float4 v1 = wr[lane + 32];
    float s = v0.x*v0.x + v0.y*v0.y + v0.z*v0.z + v0.w*v0.w
            + v1.x*v1.x + v1.y*v1.y + v1.z*v1.z + v1.w*v1.w;
    #pragma unroll
    for (int m = 16; m; m >>= 1) s += __shfl_xor_sync(0xffffffffu, s, m);
    if (lane == 0) g_cnorm[k] = s;
}

// ---------------- GEMM helpers ----------------
__device__ __forceinline__ void cp16(unsigned saddr, const void* gaddr) {
    asm volatile("cp.async.cg.shared.global [%0], [%1], 16;\n" :: "r"(saddr), "l"(gaddr) : "memory");
}
__device__ __forceinline__ void cp_commit() { asm volatile("cp.async.commit_group;\n" ::: "memory"); }
template<int P> __device__ __forceinline__ void cp_wait() {
    asm volatile("cp.async.wait_group %0;\n" :: "n"(P) : "memory");
}
__device__ __forceinline__ void ldsm4(unsigned a, unsigned &r0, unsigned &r1, unsigned &r2, unsigned &r3) {
    asm volatile("ldmatrix.sync.aligned.m8n8.x4.shared.b16 {%0,%1,%2,%3}, [%4];"
                 : "=r"(r0), "=r"(r1), "=r"(r2), "=r"(r3) : "r"(a));
}
__device__ __forceinline__ void mma16816(float* c, const unsigned* a, const unsigned* b) {
    asm volatile("mma.sync.aligned.m16n8k16.row.col.f32.f16.f16.f32 "
                 "{%0,%1,%2,%3}, {%4,%5,%6,%7}, {%8,%9}, {%0,%1,%2,%3};"
                 : "+f"(c[0]), "+f"(c[1]), "+f"(c[2]), "+f"(c[3])
                 : "r"(a[0]), "r"(a[1]), "r"(a[2]), "r"(a[3]), "r"(b[0]), "r"(b[1]));
}
__device__ __forceinline__ bool lexless(float v, int i, float w, int j) {
    return v < w || (v == w && i < j);
}
__device__ __forceinline__ void top2_merge(float &v1, int &i1, float &v2, int &i2,
                                           float w1, int j1, float w2, int j2) {
    if (lexless(w1, j1, v1, i1)) {
        float nv2; int ni2;
        if (lexless(v1, i1, w2, j2)) { nv2 = v1; ni2 = i1; } else { nv2 = w2; ni2 = j2; }
        v1 = w1; i1 = j1; v2 = nv2; i2 = ni2;
    } else if (lexless(w1, j1, v2, i2)) {
        v2 = w1; i2 = j1;
    }
}

// load one BK=64 k-stage into smem buffers
__device__ __forceinline__ void load_stage(unsigned asmem, unsigned bsmem,
                                           int rowBase, int kc, int ks, int tid) {
    int col = ks * BK;
    #pragma unroll
    for (int it = 0; it < 4; it++) {
        int c = tid + it * 256;              // 1024 chunks of 16B per operand
        int r = c >> 3, s = c & 7;
        cp16(asmem + (unsigned)((r * ASTRIDE + s * 8) * 2),
             &g_zh[(size_t)(rowBase + r) * DDIM + col + s * 8]);
        cp16(bsmem + (unsigned)((r * ASTRIDE + s * 8) * 2),
             &g_wh[(size_t)(kc + r) * DDIM + col + s * 8]);
    }
    cp_commit();
}

// ---------------- main fp16 GEMM + certified top2 ----------------
__global__ void __launch_bounds__(256, 2)
gemm_kernel(int N, int K)
{
    extern __shared__ __align__(16) __half dynsmem[];
    __half* As = dynsmem;                       // [2][BM*ASTRIDE]
    __half* Bs = dynsmem + 2 * BM * ASTRIDE;
    __shared__ float4 s_part[2][BM];
    __shared__ float4 s_run[BM];
    __shared__ float  s_cn[BN];

    const int tid  = threadIdx.x;
    const int lane = tid & 31;
    const int warp = tid >> 5;
    const int mw   = warp & 3;          // 4 m-warps
    const int nw   = warp >> 2;         // 2 n-warps
    const int wm0  = mw * 32;
    const int wn0  = nw * 64;
    const int rowBase = blockIdx.x * BM;

    unsigned asmem = (unsigned)__cvta_generic_to_shared(As);
    unsigned bsmem = (unsigned)__cvta_generic_to_shared(Bs);
    const unsigned TBYTES = BM * ASTRIDE * 2;

    if (tid < BM) s_run[tid] = make_float4(INFV, __int_as_float(0x7fffffff),
                                           INFV, __int_as_float(0x7fffffff));

    load_stage(asmem, bsmem, rowBase, 0, 0, tid);

    for (int kc = 0; kc < K; kc += BN) {
        if (tid < BN) s_cn[tid] = g_cnorm[kc + tid];

        float acc[2][8][4];
        #pragma unroll
        for (int i = 0; i < 2; i++)
            #pragma unroll
            for (int j = 0; j < 8; j++)
                #pragma unroll
                for (int c = 0; c < 4; c++) acc[i][j][c] = 0.f;

        for (int ks = 0; ks < KS; ks++) {
            int buf = ks & 1;
            cp_wait<0>();
            __syncthreads();
            if (ks + 1 < KS) {
                load_stage(asmem + (buf ^ 1) * TBYTES, bsmem + (buf ^ 1) * TBYTES,
                           rowBase, kc, ks + 1, tid);
            } else if (kc + BN < K) {
                load_stage(asmem + (buf ^ 1) * TBYTES, bsmem + (buf ^ 1) * TBYTES,
                           rowBase, kc + BN, 0, tid);
            }

            unsigned abase = asmem + buf * TBYTES;
            unsigned bbase = bsmem + buf * TBYTES;
            #pragma unroll
            for (int kk = 0; kk < BK; kk += 16) {
                unsigned a[2][4];
                #pragma unroll
                for (int i = 0; i < 2; i++) {
                    int arow = wm0 + i * 16 + (lane & 15);
                    int acol = kk + ((lane >> 4) << 3);
                    ldsm4(abase + (unsigned)((arow * ASTRIDE + acol) * 2),
                          a[i][0], a[i][1], a[i][2], a[i][3]);
                }
                unsigned b[8][2];
                #pragma unroll
                for (int p = 0; p < 4; p++) {
                    int brow = wn0 + p * 16 + (lane & 7) + ((lane >> 4) << 3);
                    int bcol = kk + (((lane >> 3) & 1) << 3);
                    ldsm4(bbase + (unsigned)((brow * ASTRIDE + bcol) * 2),
                          b[2*p][0], b[2*p][1], b[2*p+1][0], b[2*p+1][1]);
                }
                #pragma unroll
                for (int i = 0; i < 2; i++)
                    #pragma unroll
                    for (int j = 0; j < 8; j++)
                        mma16816(acc[i][j], a[i], b[j]);
            }
        }
        __syncthreads();

        // ---- epilogue: per-row top2 over this 128-code chunk ----
        #pragma unroll
        for (int i = 0; i < 2; i++) {
            #pragma unroll
            for (int h = 0; h < 2; h++) {
                float v1 = INFV; int i1 = 0x7fffffff;
                float v2 = INFV; int i2 = 0x7fffffff;
                #pragma unroll
                for (int j = 0; j < 8; j++) {
                    #pragma unroll
                    for (int c = 0; c < 2; c++) {
                        int col = wn0 + j * 8 + (lane & 3) * 2 + c;
                        float val = fmaf(-2.f, acc[i][j][h * 2 + c], s_cn[col]);
                        int idx = kc + col;
                        if (lexless(val, idx, v1, i1)) { v2 = v1; i2 = i1; v1 = val; i1 = idx; }
                        else if (lexless(val, idx, v2, i2)) { v2 = val; i2 = idx; }
                    }
                }
                #pragma unroll
                for (int off = 1; off < 4; off <<= 1) {
                    float ov1 = __shfl_xor_sync(0xffffffffu, v1, off);
                    int   oi1 = __shfl_xor_sync(0xffffffffu, i1, off);
                    float ov2 = __shfl_xor_sync(0xffffffffu, v2, off);
                    int   oi2 = __shfl_xor_sync(0xffffffffu, i2, off);
                    top2_merge(v1, i1, v2, i2, ov1, oi1, ov2, oi2);
                }
                if ((lane & 3) == 0) {
                    int r = wm0 + i * 16 + (lane >> 2) + h * 8;
                    s_part[nw][r] = make_float4(v1, __int_as_float(i1), v2, __int_as_float(i2));
                }
            }
        }
        __syncthreads();
        if (tid < BM) {
            float4 pa = s_part[0][tid];
            float4 pb = s_part[1][tid];
            float v1 = pa.x; int i1 = __float_as_int(pa.y);
            float v2 = pa.z; int i2 = __float_as_int(pa.w);
            top2_merge(v1, i1, v2, i2, pb.x, __float_as_int(pb.y), pb.z, __float_as_int(pb.w));
            float4 r = s_run[tid];
            float r1 = r.x; int ri1 = __float_as_int(r.y);
            float r2 = r.z; int ri2 = __float_as_int(r.w);
            top2_merge(r1, ri1, r2, ri2, v1, i1, v2, i2);
            s_run[tid] = make_float4(r1, __int_as_float(ri1), r2, __int_as_float(ri2));
        }
        __syncthreads();
    }

    if (tid < BM) {
        float4 r = s_run[tid];
        int row = rowBase + tid;
        g_idx[row] = __float_as_int(r.y);
        if (r.z - r.x <= g_me[row]) {
            int pos = atomicAdd(&g_flagcount, 1);
            g_flaglist[pos] = row;
        }
    }
}

// ---------------- exact refine of flagged rows (wT-based, FMA-bound) ----------------
__global__ void refine_kernel(const float* __restrict__ z, int K) {
    __shared__ __align__(16) float zs[8][260];
    __shared__ int   rowids[8];
    __shared__ float sbv[8][8];
    __shared__ int   sbi[8][8];

    const int tid  = threadIdx.x;
    const int lane = tid & 31;
    const int warp = tid >> 5;
    const int fcount = g_flagcount;

    for (int base = blockIdx.x * 8; base < fcount; base += gridDim.x * 8) {
        int cnt = min(8, fcount - base);
        if (tid < cnt) rowids[tid] = g_flaglist[base + tid];
        __syncthreads();
        for (int e = tid; e < cnt * 256; e += 256)
            zs[e >> 8][e & 255] = z[(size_t)rowids[e >> 8] * DDIM + (e & 255)];
        __syncthreads();

        float bv[8]; int bi[8];
        #pragma unroll
        for (int r = 0; r < 8; r++) { bv[r] = INFV; bi[r] = 0x7fffffff; }

        #pragma unroll 1
        for (int p = 0; p < 4; p++) {
            int k = p * 256 + tid;
            float acc[8];
            #pragma unroll
            for (int r = 0; r < 8; r++) acc[r] = 0.f;
            #pragma unroll 4
            for (int d4 = 0; d4 < 64; d4++) {
                float w0 = g_wt[(size_t)(d4 * 4 + 0) * KCODES + k];
                float w1 = g_wt[(size_t)(d4 * 4 + 1) * KCODES + k];
                float w2 = g_wt[(size_t)(d4 * 4 + 2) * KCODES + k];
                float w3 = g_wt[(size_t)(d4 * 4 + 3) * KCODES + k];
                #pragma unroll
                for (int r = 0; r < 8; r++) {
                    float4 zv = *(const float4*)&zs[r][d4 * 4];
                    acc[r] = fmaf(zv.x, w0, acc[r]);
                    acc[r] = fmaf(zv.y, w1, acc[r]);
                    acc[r] = fmaf(zv.z, w2, acc[r]);
                    acc[r] = fmaf(zv.w, w3, acc[r]);
                }
            }
            float cn = g_cnorm[k];
            #pragma unroll
            for (int r = 0; r < 8; r++) {
                float val = fmaf(-2.f, acc[r], cn);
                if (lexless(val, k, bv[r], bi[r])) { bv[r] = val; bi[r] = k; }
            }
        }

        #pragma unroll
        for (int r = 0; r < 8; r++) {
            float v = bv[r]; int i = bi[r];
            #pragma unroll
            for (int off = 16; off; off >>= 1) {
                float ov = __shfl_xor_sync(0xffffffffu, v, off);
                int   oi = __shfl_xor_sync(0xffffffffu, i, off);
                if (lexless(ov, oi, v, i)) { v = ov; i = oi; }
            }
            if (lane == 0) { sbv[warp][r] = v; sbi[warp][r] = i; }
        }
        __syncthreads();
        if (tid < cnt) {
            float v = sbv[0][tid]; int i = sbi[0][tid];
            #pragma unroll
            for (int wq = 1; wq < 8; wq++)
                if (lexless(sbv[wq][tid], sbi[wq][tid], v, i)) { v = sbv[wq][tid]; i = sbi[wq][tid]; }
            g_idx[rowids[tid]] = i;
        }
        __syncthreads();
    }
}

// ---------------- coalesced output assembly ----------------
__global__ void output_kernel(const float* __restrict__ z, const float* __restrict__ w,
                              float* __restrict__ out, int N)
{
    __shared__ int s_idx[OUTRPB];
    __shared__ float s_red[256];
    const int tid = threadIdx.x;
    const int base = blockIdx.x * OUTRPB;

    float* out_zq  = out + 1;
    float* out_idx = out + 1 + (size_t)N * DDIM;

    if (tid < OUTRPB) {
        int ix = g_idx[base + tid];
        s_idx[tid] = ix;
        out_idx[base + tid] = (float)ix;
    }
    __syncthreads();

    float lsum = 0.f;
    #pragma unroll 4
    for (int i = tid; i < OUTRPB * DDIM; i += 256) {
        int r = i >> 8, d = i & 255;
        float wv = w[(size_t)s_idx[r] * DDIM + d];
        float zv = z[(size_t)(base + r) * DDIM + d];
        float df = wv - zv;
        lsum += df * df;
        out_zq[(size_t)(base + r) * DDIM + d] = wv;
    }

    s_red[tid] = lsum;
    __syncthreads();
    #pragma unroll
    for (int m = 128; m; m >>= 1) {
        if (tid < m) s_red[tid] += s_red[tid + m];
        __syncthreads();
    }
    if (tid == 0) g_partial[blockIdx.x] = s_red[0];
}

__global__ void finalize_kernel(float* __restrict__ out, int nblocks, float scale) {
    __shared__ float s[512];
    int t = threadIdx.x;
    float v = 0.f;
    for (int i = t; i < nblocks; i += 512) v += g_partial[i];
    s[t] = v;
    __syncthreads();
    #pragma unroll
    for (int m = 256; m; m >>= 1) {
        if (t < m) s[t] += s[t + m];
        __syncthreads();
    }
    if (t == 0) out[0] = s[0] * scale;
}

extern "C" void kernel_launch(void* const* d_in, const int* in_sizes, int n_in,
                              void* d_out, int out_size) {
    const float* z = (const float*)d_in[0];
    const float* w = (const float*)d_in[1];
    float* out = (float*)d_out;

    int N = in_sizes[0] / DDIM;   // 65536
    int K = in_sizes[1] / DDIM;   // 1024

    const int dynsmem = 2 * 2 * BM * ASTRIDE * 2;   // 73728 B
    cudaFuncSetAttribute(gemm_kernel, cudaFuncAttributeMaxDynamicSharedMemorySize, dynsmem);

    init_kernel<<<1, 1>>>();
    quant_w_kernel<<<K / 8, 256>>>(w);
    transpose_w_kernel<<<dim3(K / 32, DDIM / 32), dim3(32, 8)>>>(w);
    cnorm_kernel<<<(K + 7) / 8, 256>>>(w, K);
    quant_z_kernel<<<N / 8, 256>>>(z);
    gemm_kernel<<<N / BM, 256, dynsmem>>>(N, K);
    refine_kernel<<<RGRID, 256>>>(z, K);
    output_kernel<<<N / OUTRPB, 256>>>(z, w, out, N);
    float scale = 0.25f / ((float)N * (float)DDIM);
    finalize_kernel<<<1, 512>>>(out, N / OUTRPB, scale);
}